// round 1
// baseline (speedup 1.0000x reference)
#include <cuda_runtime.h>
#include <cstdint>

// ============================================================================
// BLinear: out[t][o] = sum_i sign(x[t][i]) * sign(W[o][i]) + b[o]
// XNOR-popcount formulation: dot = I - 2*popcount(xb ^ wb), bit = signbit.
// ============================================================================

#define TPB 256
#define BT  128      // rows (t) per block
#define BO  64       // cols (o) per block
#define KC  64       // k-words per smem chunk (64 words = 2048 bits of K)

// Scratch (allocation-free rule: __device__ globals).
// Capacity: 1M words each = 32M bits of packed data. Needed: T*KW = 512K, O*KW = 128K.
__device__ uint32_t g_Xb [1 << 20];
__device__ uint32_t g_WbT[1 << 20];

// ----------------------------------------------------------------------------
// Binarize rows: out[w] = ballot(signbit), w-th group of 32 consecutive floats.
// Fully coalesced 128B reads per warp.
// ----------------------------------------------------------------------------
__global__ void __launch_bounds__(TPB)
binarize_rows(const float* __restrict__ x, uint32_t* __restrict__ out, int nwords)
{
    int lane = threadIdx.x & 31;
    int wid  = (blockIdx.x * blockDim.x + threadIdx.x) >> 5;
    int nw   = (gridDim.x * blockDim.x) >> 5;
    for (int w = wid; w < nwords; w += nw) {
        float v = x[(size_t)w * 32 + lane];
        unsigned m = __ballot_sync(0xffffffffu, (__float_as_uint(v) >> 31) != 0u);
        if (lane == 0) out[w] = m;
    }
}

// ----------------------------------------------------------------------------
// Binarize W into a TRANSPOSED bit matrix: outT[k][o] = word k of W row o.
// Each warp task = one (o, k): coalesced 128B read, single scattered word write.
// ----------------------------------------------------------------------------
__global__ void __launch_bounds__(TPB)
binarize_wT(const float* __restrict__ W, uint32_t* __restrict__ outT, int O, int KW)
{
    int lane  = threadIdx.x & 31;
    int wid   = (blockIdx.x * blockDim.x + threadIdx.x) >> 5;
    int nw    = (gridDim.x * blockDim.x) >> 5;
    int ntask = O * KW;
    int I     = KW * 32;
    for (int t = wid; t < ntask; t += nw) {
        int o = t / KW;
        int k = t - o * KW;
        float v = W[(size_t)o * I + (size_t)k * 32 + lane];
        unsigned m = __ballot_sync(0xffffffffu, (__float_as_uint(v) >> 31) != 0u);
        if (lane == 0) outT[(size_t)k * O + o] = m;
    }
}

// ----------------------------------------------------------------------------
// Popcount GEMM.
// Block tile: BT x BO. Thread tile: 8 rows x 4 cols (256 threads = 16x16 grid).
// sX: [BT][KC] row-major (a-loads broadcast within warp, <=2-way conflict)
// sW: [KC][BO] k-major   (b-loads stride 4 words across 16 tx, <=2-way conflict)
// ----------------------------------------------------------------------------
__global__ void __launch_bounds__(TPB, 2)
bgemm_popc(const uint32_t* __restrict__ Xb, const uint32_t* __restrict__ WbT,
           const float* __restrict__ bias, float* __restrict__ out,
           int T, int O, int KW)
{
    __shared__ uint32_t sX[BT * KC];   // 32 KB
    __shared__ uint32_t sW[KC * BO];   // 16 KB

    const int tid = threadIdx.x;
    const int tx  = tid & 15;          // col group
    const int ty  = tid >> 4;          // row group
    const int t0  = blockIdx.y * BT;
    const int o0  = blockIdx.x * BO;

    int acc[8][4];
#pragma unroll
    for (int i = 0; i < 8; i++)
#pragma unroll
        for (int j = 0; j < 4; j++) acc[i][j] = 0;

    for (int kc = 0; kc < KW; kc += KC) {
        // ---- load X tile (BT rows x KC words), uint4 per thread-iter ----
#pragma unroll
        for (int i = tid; i < BT * (KC / 4); i += TPB) {
            int r  = i >> 4;            // / (KC/4)
            int kq = (i & 15) << 2;     // word offset in chunk
            uint4 v = make_uint4(0u, 0u, 0u, 0u);
            int row = t0 + r;
            int kw  = kc + kq;
            if (row < T && kw + 3 < KW) {
                v = *(const uint4*)&Xb[(size_t)row * KW + kw];
            } else if (row < T) {
                uint32_t tmp[4] = {0u, 0u, 0u, 0u};
                for (int q = 0; q < 4; q++)
                    if (kw + q < KW) tmp[q] = Xb[(size_t)row * KW + kw + q];
                v = make_uint4(tmp[0], tmp[1], tmp[2], tmp[3]);
            }
            *(uint4*)&sX[r * KC + kq] = v;
        }
        // ---- load W tile (KC k-rows x BO cols), transposed source ----
#pragma unroll
        for (int i = tid; i < KC * (BO / 4); i += TPB) {
            int k  = i >> 4;            // / (BO/4)
            int cq = (i & 15) << 2;
            uint4 v = make_uint4(0u, 0u, 0u, 0u);
            int kw  = kc + k;
            int col = o0 + cq;
            if (kw < KW) {
                if (col + 3 < O) {
                    v = *(const uint4*)&WbT[(size_t)kw * O + col];
                } else {
                    uint32_t tmp[4] = {0u, 0u, 0u, 0u};
                    for (int q = 0; q < 4; q++)
                        if (col + q < O) tmp[q] = WbT[(size_t)kw * O + col + q];
                    v = make_uint4(tmp[0], tmp[1], tmp[2], tmp[3]);
                }
            }
            *(uint4*)&sW[k * BO + cq] = v;
        }
        __syncthreads();

        // ---- accumulate: 4 k-words per step ----
        const int kend = (KW - kc < KC) ? (KW - kc) : KC;
        for (int k4 = 0; k4 < kend; k4 += 4) {
            uint32_t a[8][4];
#pragma unroll
            for (int i = 0; i < 8; i++)
                *(uint4*)a[i] = *(const uint4*)&sX[(ty * 8 + i) * KC + k4];
            uint32_t b[4][4];
#pragma unroll
            for (int kk = 0; kk < 4; kk++)
                *(uint4*)b[kk] = *(const uint4*)&sW[(k4 + kk) * BO + tx * 4];
#pragma unroll
            for (int kk = 0; kk < 4; kk++)
#pragma unroll
                for (int i = 0; i < 8; i++) {
                    uint32_t av = a[i][kk];
#pragma unroll
                    for (int j = 0; j < 4; j++)
                        acc[i][j] += __popc(av ^ b[kk][j]);
                }
        }
        __syncthreads();
    }

    // ---- epilogue: dot = Kbits - 2*popc, add bias, fp32 out ----
    const int Kbits = KW * 32;
    float bv[4];
#pragma unroll
    for (int j = 0; j < 4; j++) {
        int c = o0 + tx * 4 + j;
        bv[j] = (c < O) ? bias[c] : 0.0f;
    }
    const int c0 = o0 + tx * 4;
#pragma unroll
    for (int i = 0; i < 8; i++) {
        int row = t0 + ty * 8 + i;
        if (row >= T) continue;
        if (c0 + 3 < O) {
            float4 v;
            v.x = (float)(Kbits - 2 * acc[i][0]) + bv[0];
            v.y = (float)(Kbits - 2 * acc[i][1]) + bv[1];
            v.z = (float)(Kbits - 2 * acc[i][2]) + bv[2];
            v.w = (float)(Kbits - 2 * acc[i][3]) + bv[3];
            *(float4*)&out[(size_t)row * O + c0] = v;
        } else {
            for (int j = 0; j < 4; j++)
                if (c0 + j < O)
                    out[(size_t)row * O + c0 + j] =
                        (float)(Kbits - 2 * acc[i][j]) + bv[j];
        }
    }
}

// ----------------------------------------------------------------------------
// Launch
// ----------------------------------------------------------------------------
extern "C" void kernel_launch(void* const* d_in, const int* in_sizes, int n_in,
                              void* d_out, int out_size)
{
    const float* x = (const float*)d_in[0];
    const float* W = (const float*)d_in[1];
    const float* b = (const float*)d_in[2];
    float* out = (float*)d_out;

    const int O  = in_sizes[2];              // out_features (bias length)
    const int I  = in_sizes[1] / O;          // in_features
    const int T  = in_sizes[0] / I;          // batch rows
    const int KW = I / 32;                   // packed words per row (I % 32 == 0)

    uint32_t* Xb;
    uint32_t* WbT;
    cudaGetSymbolAddress((void**)&Xb,  g_Xb);
    cudaGetSymbolAddress((void**)&WbT, g_WbT);

    // 1) binarize x rows -> bit matrix [T][KW]
    {
        int nwords = T * KW;
        int blocks = 1024;
        binarize_rows<<<blocks, TPB>>>(x, Xb, nwords);
    }
    // 2) binarize W -> transposed bit matrix [KW][O]
    {
        int blocks = 512;
        binarize_wT<<<blocks, TPB>>>(W, WbT, O, KW);
    }
    // 3) popcount GEMM + bias
    {
        dim3 grid((O + BO - 1) / BO, (T + BT - 1) / BT);
        bgemm_popc<<<grid, TPB>>>(Xb, WbT, b, out, T, O, KW);
    }
}

// round 4
// speedup vs baseline: 2.4684x; 2.4684x over previous
#include <cuda_runtime.h>
#include <cstdint>

// ============================================================================
// BLinear: out[t][o] = sum_i sign(x[t,i])*sign(W[o,i]) + b[o]
// Target sm_100 (non-'a': no tcgen05). Path: s8 +-1 encode -> mma.sync
// m16n8k32 s32 IMMA GEMM -> float + bias. All-integer accumulation is exact.
// ============================================================================

#define TPB 256
#define TM 128
#define TN 128
#define TKB 64                    // K bytes per stage
#define STAGES 5

#define A_BYTES (TM * TKB)        // 8192
#define STAGE_BYTES (2 * A_BYTES) // 16384 (A then B)
#define SMEM_TOTAL (STAGES * STAGE_BYTES)   // 81920

// Scratch (allocation rules: __device__ globals)
__device__ __align__(256) int8_t g_Xa[8192u * 2048u];   // 16 MB packed x
__device__ __align__(256) int8_t g_Wb[2048u * 2048u];   //  4 MB packed W

__device__ __forceinline__ uint32_t smem_u32(const void* p) {
    uint32_t a;
    asm("{ .reg .u64 t; cvta.to.shared.u64 t, %1; cvt.u32.u64 %0, t; }"
        : "=r"(a) : "l"(p));
    return a;
}
__device__ __forceinline__ void cp16(uint32_t dst, const void* src) {
    asm volatile("cp.async.cg.shared.global [%0], [%1], 16;"
        :: "r"(dst), "l"(src) : "memory");
}
#define CP_COMMIT() asm volatile("cp.async.commit_group;" ::: "memory")
#define CP_WAIT(n)  asm volatile("cp.async.wait_group %0;" :: "n"(n) : "memory")

__device__ __forceinline__ void ldm_x4(uint32_t& r0, uint32_t& r1,
                                       uint32_t& r2, uint32_t& r3, uint32_t addr) {
    asm volatile("ldmatrix.sync.aligned.m8n8.x4.shared.b16 {%0,%1,%2,%3}, [%4];"
        : "=r"(r0), "=r"(r1), "=r"(r2), "=r"(r3) : "r"(addr));
}
__device__ __forceinline__ void imma(int* d, const uint32_t* a, const uint32_t* b) {
    asm volatile("mma.sync.aligned.m16n8k32.row.col.s32.s8.s8.s32 "
        "{%0,%1,%2,%3}, {%4,%5,%6,%7}, {%8,%9}, {%0,%1,%2,%3};"
        : "+r"(d[0]), "+r"(d[1]), "+r"(d[2]), "+r"(d[3])
        : "r"(a[0]), "r"(a[1]), "r"(a[2]), "r"(a[3]), "r"(b[0]), "r"(b[1]));
}

// 16B-chunk XOR swizzle within a 64B k-row: conflict-free for cp.async stores
// and for ldmatrix 8-row read phases.
__device__ __forceinline__ uint32_t swz(int r, int c) {
    return (uint32_t)(r * TKB + ((c ^ ((r >> 1) & 3)) << 4));
}

// ---------------------------------------------------------------------------
// Pack fp32 -> s8 sign (+1 -> 0x01, -1 -> 0xFF); 16 bytes out per iter
// ---------------------------------------------------------------------------
__global__ void __launch_bounds__(TPB)
pack_s8(const float* __restrict__ src, int8_t* __restrict__ dst, int n16)
{
    int idx = blockIdx.x * blockDim.x + threadIdx.x;
    int stride = gridDim.x * blockDim.x;
    const float4* s4 = (const float4*)src;
    uint4* d4 = (uint4*)dst;
    for (int i = idx; i < n16; i += stride) {
        uint32_t w[4];
#pragma unroll
        for (int k = 0; k < 4; k++) {
            float4 f = s4[(size_t)i * 4 + k];
            uint32_t sb = (__float_as_uint(f.x) >> 31)
                        | ((__float_as_uint(f.y) >> 31) << 8)
                        | ((__float_as_uint(f.z) >> 31) << 16)
                        | ((__float_as_uint(f.w) >> 31) << 24);
            w[k] = 0x01010101u ^ (sb * 0xFEu);   // per byte: 0x01 or 0xFF
        }
        d4[i] = make_uint4(w[0], w[1], w[2], w[3]);
    }
}

// ---------------------------------------------------------------------------
// IMMA GEMM: out[T,O] = A[T,K]s8 @ B[O,K]s8^T (as s32) + bias, fp32 out.
// Block 128x128, 8 warps of 64x32, 5-stage cp.async pipeline.
// ---------------------------------------------------------------------------
__global__ void __launch_bounds__(TPB, 2)
bgemm_imma(const int8_t* __restrict__ A, const int8_t* __restrict__ B,
           const float* __restrict__ bias, float* __restrict__ out,
           int T, int O, int Kb)
{
    extern __shared__ char smem[];
    const uint32_t sm = smem_u32(smem);
    const int tid  = threadIdx.x;
    const int wid  = tid >> 5;
    const int lane = tid & 31;
    const int m0 = blockIdx.y * TM;
    const int n0 = blockIdx.x * TN;
    const int KCH = Kb / TKB;

    const int warp_m = (wid & 1) * 64;    // 2 m-groups
    const int warp_n = (wid >> 1) * 32;   // 4 n-groups

    // per-lane ldmatrix source offsets (stage-relative), both ksteps
    const int mat = lane >> 3, rin = lane & 7;
    uint32_t relA[4][2], relB[2][2];
#pragma unroll
    for (int mf = 0; mf < 4; mf++) {
        int r = warp_m + mf * 16 + (mat & 1) * 8 + rin;
        int cpar = mat >> 1;
#pragma unroll
        for (int ks = 0; ks < 2; ks++)
            relA[mf][ks] = swz(r, 2 * ks + cpar);
    }
#pragma unroll
    for (int g = 0; g < 2; g++) {
        int r = warp_n + g * 16 + (mat >> 1) * 8 + rin;
        int cpar = mat & 1;
#pragma unroll
        for (int ks = 0; ks < 2; ks++)
            relB[g][ks] = (uint32_t)A_BYTES + swz(r, 2 * ks + cpar);
    }

    const int8_t* gA = A + (size_t)m0 * Kb;
    const int8_t* gB = B + (size_t)n0 * Kb;

    // cp.async task split: i<512 -> A (r=i>>2,c=i&3), else B
    const int i0 = tid;                    // + k*TPB, k=0..3
    auto load_stage = [&](int slot, int ch) {
        uint32_t sbase = sm + slot * STAGE_BYTES;
        size_t koff = (size_t)ch * TKB;
#pragma unroll
        for (int k = 0; k < 4; k++) {
            int i = i0 + k * TPB;
            if (i < 512) {
                int r = i >> 2, c = i & 3;
                cp16(sbase + swz(r, c), gA + (size_t)r * Kb + koff + c * 16);
            } else {
                int j = i - 512;
                int r = j >> 2, c = j & 3;
                cp16(sbase + A_BYTES + swz(r, c),
                     gB + (size_t)r * Kb + koff + c * 16);
            }
        }
    };

    int acc[4][4][4];
#pragma unroll
    for (int a = 0; a < 4; a++)
#pragma unroll
        for (int b = 0; b < 4; b++)
#pragma unroll
            for (int c = 0; c < 4; c++) acc[a][b][c] = 0;

    // prologue: fill stages 0..3
#pragma unroll
    for (int s = 0; s < STAGES - 1; s++) {
        load_stage(s, s);
        CP_COMMIT();
    }

    for (int it = 0; it < KCH; it++) {
        const int slot = it % STAGES;
        CP_WAIT(STAGES - 2);
        __syncthreads();

        const uint32_t sbase = sm + slot * STAGE_BYTES;
#pragma unroll
        for (int ks = 0; ks < 2; ks++) {
            uint32_t a[4][4], b[2][4];
#pragma unroll
            for (int mf = 0; mf < 4; mf++)
                ldm_x4(a[mf][0], a[mf][1], a[mf][2], a[mf][3],
                       sbase + relA[mf][ks]);
#pragma unroll
            for (int g = 0; g < 2; g++)
                ldm_x4(b[g][0], b[g][1], b[g][2], b[g][3],
                       sbase + relB[g][ks]);
#pragma unroll
            for (int mf = 0; mf < 4; mf++)
#pragma unroll
                for (int nf = 0; nf < 4; nf++)
                    imma(acc[mf][nf], a[mf], &b[nf >> 1][(nf & 1) * 2]);
        }

        const int ld = it + STAGES - 1;
        if (ld < KCH) load_stage(ld % STAGES, ld);
        CP_COMMIT();
    }

    // epilogue: s32 -> fp32 + bias, float2 stores (32B per quad, coalesced)
    const int rbase = m0 + warp_m + (lane >> 2);
    const int cbase = n0 + warp_n + (lane & 3) * 2;
#pragma unroll
    for (int nf = 0; nf < 4; nf++) {
        const int col = cbase + nf * 8;
        const float2 bv = *(const float2*)&bias[col];
#pragma unroll
        for (int mf = 0; mf < 4; mf++) {
            const int r0 = rbase + mf * 16;
            float2 v0, v1;
            v0.x = (float)acc[mf][nf][0] + bv.x;
            v0.y = (float)acc[mf][nf][1] + bv.y;
            v1.x = (float)acc[mf][nf][2] + bv.x;
            v1.y = (float)acc[mf][nf][3] + bv.y;
            *(float2*)&out[(size_t)r0 * O + col] = v0;
            *(float2*)&out[(size_t)(r0 + 8) * O + col] = v1;
        }
    }
}

// ---------------------------------------------------------------------------
// Launch
// ---------------------------------------------------------------------------
extern "C" void kernel_launch(void* const* d_in, const int* in_sizes, int n_in,
                              void* d_out, int out_size)
{
    const float* x = (const float*)d_in[0];
    const float* W = (const float*)d_in[1];
    const float* b = (const float*)d_in[2];
    float* out = (float*)d_out;

    const int O = in_sizes[2];            // out_features
    const int I = in_sizes[1] / O;        // in_features (K)
    const int T = in_sizes[0] / I;        // batch rows

    int8_t *Xa, *Wb;
    cudaGetSymbolAddress((void**)&Xa, g_Xa);
    cudaGetSymbolAddress((void**)&Wb, g_Wb);

    cudaFuncSetAttribute(bgemm_imma,
                         cudaFuncAttributeMaxDynamicSharedMemorySize, SMEM_TOTAL);

    pack_s8<<<2048, TPB>>>(x, Xa, (T * I) / 16);
    pack_s8<<<512,  TPB>>>(W, Wb, (O * I) / 16);

    dim3 grid(O / TN, T / TM);
    bgemm_imma<<<grid, TPB, SMEM_TOTAL>>>(Xa, Wb, b, out, T, O, I);
}